// round 10
// baseline (speedup 1.0000x reference)
#include <cuda_runtime.h>
#include <cuda_fp16.h>

// Multi-scale deformable attention, fully fused (round 10).
// Fixed constants: BS=2, NQ=32768, C=128, NH=1, NL=2, NP=8
//   level 0: H=128,W=256,start=0 ; level 1: H=64,W=128,start=32768 ; NV=40960
//
// R10: compact 16B sample records (1 LDS/sample), fp16-packed W_out tile
//      table (Phase C Wout 16->2 wf per k4), occupancy 4->5 CTAs/SM.

namespace {

constexpr int BSZ   = 2;
constexpr int NQ    = 32768;
constexpr int CH    = 128;
constexpr int NV    = 40960;
constexpr int NSAMP = 16;   // NL*NP
constexpr int NOFF  = 32;   // NL*NP*2
constexpr int WARPS = 8;    // warps per CTA
constexpr int QPW   = 4;    // queries per warp
constexpr int QPC   = WARPS * QPW;   // 32 queries per CTA

constexpr size_t VAL_ELEMS = (size_t)BSZ * NV * CH;   // 10,485,760

typedef unsigned long long ull;

__device__ __half g_val_h[VAL_ELEMS];                 // 21 MB scratch
// Packed projection weights: [k/2][sample j] = 8 fp16:
//   {offx(k0,j), offy(k0,j), attn(k0,j), 0, offx(k1,j), offy(k1,j), attn(k1,j), 0}
__device__ uint4 g_wpack[CH / 2][NSAMP];
// Packed fp16 W_out tiles: [k4][wc] -> 2x uint4 = 16 fp16 = rows 4k4..4k4+3,
// cols 4wc..4wc+3.  half 0 = rows {0,1}, half 1 = rows {2,3}; each row is
// (half2 cols{0,1}, half2 cols{2,3}).
__device__ uint4 g_woutp[CH / 4][CH / 4][2];          // 32 KB

// ---- f32x2 helpers ---------------------------------------------------------
__device__ __forceinline__ ull pack2(float lo, float hi)
{
    ull r;
    asm("mov.b64 %0, {%1, %2};" : "=l"(r) : "f"(lo), "f"(hi));
    return r;
}
__device__ __forceinline__ float2 unpack2(ull v)
{
    float2 f;
    asm("mov.b64 {%0, %1}, %2;" : "=f"(f.x), "=f"(f.y) : "l"(v));
    return f;
}
__device__ __forceinline__ void fma2(ull& acc, ull a, ull b)
{
    asm("fma.rn.f32x2 %0, %1, %2, %0;" : "+l"(acc) : "l"(a), "l"(b));
}
// half2 (as u32) -> packed f32x2 (as u64)
__device__ __forceinline__ ull h2f2(unsigned int h)
{
    ull r;
    asm("{\n\t"
        ".reg .f16 lo, hi;\n\t"
        ".reg .f32 flo, fhi;\n\t"
        "mov.b32 {lo, hi}, %1;\n\t"
        "cvt.f32.f16 flo, lo;\n\t"
        "cvt.f32.f16 fhi, hi;\n\t"
        "mov.b64 %0, {flo, fhi};\n\t"
        "}"
        : "=l"(r) : "r"(h));
    return r;
}

// ---- prep: value fp32->fp16 + weight packing (fused) ------------------------
__global__ void __launch_bounds__(256) convert_value(
    const float* __restrict__ v,
    const float* __restrict__ Woff, const float* __restrict__ Wattn,
    const float* __restrict__ Wout)
{
    const size_t i = ((size_t)blockIdx.x * 256 + threadIdx.x) * 4;
    const float4 f = *(const float4*)(v + i);
    const __half2 h0 = __floats2half2_rn(f.x, f.y);
    const __half2 h1 = __floats2half2_rn(f.z, f.w);
    uint2 u;
    u.x = *(const unsigned int*)&h0;
    u.y = *(const unsigned int*)&h1;
    *(uint2*)(g_val_h + i) = u;

    if (blockIdx.x == 0) {
        // projection-weight packing
        for (int idx = threadIdx.x; idx < (CH / 2) * NSAMP; idx += 256) {
            const int k2 = idx >> 4;
            const int j  = idx & 15;
            const int k0 = 2 * k2, k1 = 2 * k2 + 1;
            const __half2 a0 = __floats2half2_rn(Woff[k0 * NOFF + 2 * j],
                                                 Woff[k0 * NOFF + 2 * j + 1]);
            const __half2 a1 = __floats2half2_rn(Wattn[k0 * NSAMP + j], 0.f);
            const __half2 a2 = __floats2half2_rn(Woff[k1 * NOFF + 2 * j],
                                                 Woff[k1 * NOFF + 2 * j + 1]);
            const __half2 a3 = __floats2half2_rn(Wattn[k1 * NSAMP + j], 0.f);
            uint4 w;
            w.x = *(const unsigned int*)&a0;
            w.y = *(const unsigned int*)&a1;
            w.z = *(const unsigned int*)&a2;
            w.w = *(const unsigned int*)&a3;
            g_wpack[k2][j] = w;
        }
    } else if (blockIdx.x == 1) {
        // W_out fp16 tile packing: idx over (k4, wc, half)
        for (int idx = threadIdx.x; idx < (CH / 4) * (CH / 4) * 2; idx += 256) {
            const int hf = idx & 1;
            const int wc = (idx >> 1) & 31;
            const int k4 = idx >> 6;
            const int kr = 4 * k4 + 2 * hf;
            const int col = 4 * wc;
            const __half2 p0 = __floats2half2_rn(Wout[(kr + 0) * CH + col + 0],
                                                 Wout[(kr + 0) * CH + col + 1]);
            const __half2 p1 = __floats2half2_rn(Wout[(kr + 0) * CH + col + 2],
                                                 Wout[(kr + 0) * CH + col + 3]);
            const __half2 p2 = __floats2half2_rn(Wout[(kr + 1) * CH + col + 0],
                                                 Wout[(kr + 1) * CH + col + 1]);
            const __half2 p3 = __floats2half2_rn(Wout[(kr + 1) * CH + col + 2],
                                                 Wout[(kr + 1) * CH + col + 3]);
            uint4 w;
            w.x = *(const unsigned int*)&p0;
            w.y = *(const unsigned int*)&p1;
            w.z = *(const unsigned int*)&p2;
            w.w = *(const unsigned int*)&p3;
            g_woutp[k4][wc][hf] = w;
        }
    }
}

// Accumulate 8 fp16 channels (one uint4) with weight w into 4 packed f32x2.
__device__ __forceinline__ void acc8p(ull* ac, float w, const uint4& u)
{
    const ull wd = pack2(w, w);
    fma2(ac[0], wd, h2f2(u.x));
    fma2(ac[1], wd, h2f2(u.y));
    fma2(ac[2], wd, h2f2(u.z));
    fma2(ac[3], wd, h2f2(u.w));
}

__global__ void __launch_bounds__(WARPS * 32, 5) msda_fused(
    const float* __restrict__ query,
    const float* __restrict__ qloc,
    const float* __restrict__ boff,
    const float* __restrict__ battn,
    const float* __restrict__ bout,
    float* __restrict__ out)
{
    // Dual-use buffer, padded stride 33:
    //  Phase A: row q = query vector of CTA-query q
    //  Phase B: overwritten TRANSPOSED with sampled vecs (tbuf[k4][q])
    __shared__ float4 tbuf[QPC][33];
    // Compact per-warp sample records (16B each), one set per lane-half.
    __shared__ uint4 srec[WARPS][2][NSAMP];

    const int tid  = threadIdx.x;
    const int warp = tid >> 5;
    const int lane = tid & 31;
    const int j16  = lane & 15;     // sample / channel-chunk owned by this lane
    const int qsel = lane >> 4;     // half 0 -> queries {0,1}, half 1 -> {2,3}
    const int qb   = blockIdx.x * QPC;
    const int q0   = qb + warp * QPW;
    const int b    = q0 >> 15;      // batch (uniform within CTA)

    // ---------------- Phase A: stage queries + packed-weight projections ----
    #pragma unroll
    for (int qq = 0; qq < QPW; qq++)
        tbuf[warp * QPW + qq][lane] =
            ((const float4*)(query + (size_t)(q0 + qq) * CH))[lane];
    __syncwarp();

    ull   offp[2];                  // packed (ox, oy) accumulators
    float lg[2];
    {
        const float2 b2 = *(const float2*)&boff[2 * j16];
        const float  ba = battn[j16];
        offp[0] = pack2(b2.x, b2.y);
        offp[1] = offp[0];
        lg[0] = ba; lg[1] = ba;
    }

    const int row0 = warp * QPW + 2 * qsel;

    #pragma unroll 4
    for (int k4 = 0; k4 < CH / 4; k4++) {
        const uint4 wp0 = g_wpack[2 * k4 + 0][j16];   // k = 4k4, 4k4+1
        const uint4 wp1 = g_wpack[2 * k4 + 1][j16];   // k = 4k4+2, 4k4+3
        const ull o0 = h2f2(wp0.x);
        const ull o1 = h2f2(wp0.z);
        const ull o2 = h2f2(wp1.x);
        const ull o3 = h2f2(wp1.z);
        const float a0 = __half2float(__low2half(*(const __half2*)&wp0.y));
        const float a1 = __half2float(__low2half(*(const __half2*)&wp0.w));
        const float a2 = __half2float(__low2half(*(const __half2*)&wp1.y));
        const float a3 = __half2float(__low2half(*(const __half2*)&wp1.w));
        #pragma unroll
        for (int qq = 0; qq < 2; qq++) {
            const float4 qv = tbuf[row0 + qq][k4];
            fma2(offp[qq], pack2(qv.x, qv.x), o0);
            lg[qq] = fmaf(qv.x, a0, lg[qq]);
            fma2(offp[qq], pack2(qv.y, qv.y), o1);
            lg[qq] = fmaf(qv.y, a1, lg[qq]);
            fma2(offp[qq], pack2(qv.z, qv.z), o2);
            lg[qq] = fmaf(qv.z, a2, lg[qq]);
            fma2(offp[qq], pack2(qv.w, qv.w), o3);
            lg[qq] = fmaf(qv.w, a3, lg[qq]);
        }
    }
    __syncthreads();    // all query-vector reads done before transposed stores

    // Level constants for the sample this lane owns.
    const int  l_own  = j16 >> 3;
    const int  Hl     = l_own ? 64 : 128;
    const int  Wl     = l_own ? 128 : 256;
    const int  startl = l_own ? 32768 : 0;
    // Gather base: this lane covers fp16 channels [8*j16, 8*j16+8)
    const char* vbh = (const char*)g_val_h + (size_t)b * NV * CH * 2 + j16 * 16;

    uint4 (*recw)[NSAMP] = srec[warp];

    // ---------------- Phase B: 2 passes; each half gathers its own query ----
    #pragma unroll 1
    for (int t = 0; t < 2; t++) {
        __syncwarp();   // records of previous pass fully consumed

        const int qi_own = q0 + 2 * qsel + t;

        // softmax over 16 samples within each lane-half
        float l0 = lg[t];
        float m = l0;
        #pragma unroll
        for (int o = 8; o >= 1; o >>= 1)
            m = fmaxf(m, __shfl_xor_sync(0xffffffffu, m, o));
        const float e = __expf(l0 - m);
        float se = e;
        #pragma unroll
        for (int o = 8; o >= 1; o >>= 1)
            se += __shfl_xor_sync(0xffffffffu, se, o);
        const float aw = e / se;

        // Compact per-lane sample record (32 records / 2 queries at once).
        {
            const float2 ofa = unpack2(offp[t]);
            const float4 lv = *(const float4*)(qloc + (size_t)qi_own * 4);
            const float x = (l_own ? lv.z : lv.x) * (float)Wl + ofa.x - 0.5f;
            const float y = (l_own ? lv.w : lv.y) * (float)Hl + ofa.y - 0.5f;
            const float xf = floorf(x), yf = floorf(y);
            const int   x0 = (int)xf,   y0 = (int)yf;
            const float lx = x - xf,    ly = y - yf;

            const bool vx0 = (unsigned)x0 < (unsigned)Wl;
            const bool vx1 = (unsigned)(x0 + 1) < (unsigned)Wl;
            const bool vy0 = (unsigned)y0 < (unsigned)Hl;
            const bool vy1 = (unsigned)(y0 + 1) < (unsigned)Hl;

            const float w00 = (vx0 && vy0) ? (1.f - lx) * (1.f - ly) * aw : 0.f;
            const float w10 = (vx1 && vy0) ? lx * (1.f - ly) * aw : 0.f;
            const float w01 = (vx0 && vy1) ? (1.f - lx) * ly * aw : 0.f;
            const float w11 = (vx1 && vy1) ? lx * ly * aw : 0.f;

            const int cx0 = min(max(x0, 0), Wl - 1);
            const int cx1 = min(max(x0 + 1, 0), Wl - 1);
            const int cy0 = min(max(y0, 0), Hl - 1) * Wl + startl;
            const int cy1 = min(max(y0 + 1, 0), Hl - 1) * Wl + startl;

            // corner deltas are exact: clamped corner -> delta 0 -> weight 0
            uint4 r;
            r.x = (unsigned)((cy0 + cx0) << 8);           // o00 bytes (256B rows)
            r.y = (unsigned)(cx1 - cx0) | ((unsigned)(cy1 - cy0) << 16);
            const __half2 hA = __floats2half2_rn(w00, w10);
            const __half2 hB = __floats2half2_rn(w01, w11);
            r.z = *(const unsigned int*)&hA;
            r.w = *(const unsigned int*)&hB;
            recw[qsel][j16] = r;
        }
        __syncwarp();

        // Gather: 1 LDS.128 per sample, 4 LDG.128 per sample (per half).
        ull ac[4];
        ac[0] = ac[1] = ac[2] = ac[3] = pack2(0.f, 0.f);
        #pragma unroll
        for (int s = 0; s < NSAMP; s++) {
            const uint4 r = recw[qsel][s];
            const int o00 = (int)r.x;
            const int dx  = (int)(r.y & 0xffffu) << 8;
            const int dy  = (int)(r.y >> 16) << 8;
            const float2 wA = __half22float2(*(const __half2*)&r.z); // w00, w10
            const float2 wB = __half22float2(*(const __half2*)&r.w); // w01, w11
            const uint4 u00 = *(const uint4*)(vbh + o00);
            const uint4 u10 = *(const uint4*)(vbh + o00 + dx);
            const uint4 u01 = *(const uint4*)(vbh + o00 + dy);
            const uint4 u11 = *(const uint4*)(vbh + o00 + dx + dy);
            acc8p(ac, wA.x, u00);
            acc8p(ac, wA.y, u10);
            acc8p(ac, wB.x, u01);
            acc8p(ac, wB.y, u11);
        }

        // Transposed stash: lane owns channels 8*j16.. -> rows k4 = 2*j16, +1.
        const int qidx = warp * QPW + 2 * qsel + t;
        const float2 p0 = unpack2(ac[0]);
        const float2 p1 = unpack2(ac[1]);
        const float2 p2 = unpack2(ac[2]);
        const float2 p3 = unpack2(ac[3]);
        tbuf[2 * j16 + 0][qidx] = make_float4(p0.x, p0.y, p1.x, p1.y);
        tbuf[2 * j16 + 1][qidx] = make_float4(p2.x, p2.y, p3.x, p3.y);
    }
    __syncthreads();    // all sampled vectors visible CTA-wide

    // ---------------- Phase C: CTA-cooperative output projection ------------
    // Warp w owns output cols [16w,16w+16).  Lane tile: 4 queries x 4 cols.
    // W_out read as fp16 tiles (2 LDG.128 per k4, dedup across qg lanes).
    {
        const int qg = lane >> 2;               // query group 0..7
        const int cg = lane & 3;                // col group  0..3
        const int wc = warp * 4 + cg;           // tile column index
        const int colbase = wc * 4;
        const int qrow = 4 * qg;

        const float4 bo = *(const float4*)&bout[colbase];
        // a_lo[q] = packed cols {0,1}; a_hi[q] = packed cols {2,3}
        ull a_lo[4], a_hi[4];
        #pragma unroll
        for (int q = 0; q < 4; q++) {
            a_lo[q] = pack2(bo.x, bo.y);
            a_hi[q] = pack2(bo.z, bo.w);
        }

        #pragma unroll 2
        for (int k4 = 0; k4 < CH / 4; k4++) {
            const float4 s0 = tbuf[k4][qrow + 0];
            const float4 s1 = tbuf[k4][qrow + 1];
            const float4 s2 = tbuf[k4][qrow + 2];
            const float4 s3 = tbuf[k4][qrow + 3];
            const uint4 wA = g_woutp[k4][wc][0];   // rows 0,1 of the k-tile
            const uint4 wB = g_woutp[k4][wc][1];   // rows 2,3

            ull d, wl, wh;
            wl = h2f2(wA.x); wh = h2f2(wA.y);      // row 0
            d = pack2(s0.x, s0.x); fma2(a_lo[0], d, wl); fma2(a_hi[0], d, wh);
            d = pack2(s1.x, s1.x); fma2(a_lo[1], d, wl); fma2(a_hi[1], d, wh);
            d = pack2(s2.x, s2.x); fma2(a_lo[2], d, wl); fma2(a_hi[2], d, wh);
            d = pack2(s3.x, s3.x); fma2(a_lo[3], d, wl); fma2(a_hi[3], d, wh);

            wl = h2f2(wA.z); wh = h2f2(wA.w);      // row 1
            d = pack2(s0.y, s0.y); fma2(a_lo[0], d, wl); fma2(a_hi[0], d, wh);
            d = pack2(s1.y, s1.y); fma2(a_lo[1], d, wl); fma2(a_hi[1], d, wh);
            d = pack2(s2.y, s2.y); fma2(a_lo[2], d, wl); fma2(a_hi[2], d, wh);
            d = pack2(s3.y, s3.y); fma2(a_lo[3], d, wl); fma2(a_hi[3], d, wh);

            wl = h2f2(wB.x); wh = h2f2(wB.y);      // row 2
            d = pack2(s0.z, s0.z); fma2(a_lo[0], d, wl); fma2(a_hi[0], d, wh);
            d = pack2(s1.z, s1.z); fma2(a_lo[1], d, wl); fma2(a_hi[1], d, wh);
            d = pack2(s2.z, s2.z); fma2(a_lo[2], d, wl); fma2(a_hi[2], d, wh);
            d = pack2(s3.z, s3.z); fma2(a_lo[3], d, wl); fma2(a_hi[3], d, wh);

            wl = h2f2(wB.z); wh = h2f2(wB.w);      // row 3
            d = pack2(s0.w, s0.w); fma2(a_lo[0], d, wl); fma2(a_hi[0], d, wh);
            d = pack2(s1.w, s1.w); fma2(a_lo[1], d, wl); fma2(a_hi[1], d, wh);
            d = pack2(s2.w, s2.w); fma2(a_lo[2], d, wl); fma2(a_hi[2], d, wh);
            d = pack2(s3.w, s3.w); fma2(a_lo[3], d, wl); fma2(a_hi[3], d, wh);
        }

        float* ob = out + (size_t)(qb + qrow) * CH + colbase;
        #pragma unroll
        for (int q = 0; q < 4; q++) {
            const float2 lo = unpack2(a_lo[q]);
            const float2 hi = unpack2(a_hi[q]);
            *(float4*)(ob + q * CH) = make_float4(lo.x, lo.y, hi.x, hi.y);
        }
    }
}

} // namespace

extern "C" void kernel_launch(void* const* d_in, const int* in_sizes, int n_in,
                              void* d_out, int out_size)
{
    const float* query = (const float*)d_in[0];
    const float* value = (const float*)d_in[1];
    const float* qloc  = (const float*)d_in[2];
    const float* Woff  = (const float*)d_in[5];
    const float* boff  = (const float*)d_in[6];
    const float* Wattn = (const float*)d_in[7];
    const float* battn = (const float*)d_in[8];
    const float* Wout  = (const float*)d_in[9];
    const float* bout  = (const float*)d_in[10];

    // Fused prep: value fp32 -> fp16 + projection/output weight packing
    constexpr int conv_blocks = (int)(VAL_ELEMS / 4 / 256);   // 10240
    convert_value<<<conv_blocks, 256>>>(value, Woff, Wattn, Wout);

    constexpr int blocks = (BSZ * NQ) / QPC;     // 2048
    msda_fused<<<blocks, WARPS * 32>>>(query, qloc, boff, battn,
                                       bout, (float*)d_out);
}

// round 11
// speedup vs baseline: 1.0419x; 1.0419x over previous
#include <cuda_runtime.h>
#include <cuda_fp16.h>
#include <mma.h>

// Multi-scale deformable attention, fully fused (round 11).
// Fixed constants: BS=2, NQ=32768, C=128, NH=1, NL=2, NP=8
//   level 0: H=128,W=256,start=0 ; level 1: H=64,W=128,start=32768 ; NV=40960
//
// R11: Phase A/B = round-9 config (fp32 records).  Phase C moved to tensor
//      cores: sampled vectors stashed fp16 row-major in SMEM, out-projection
//      done with wmma m16n16k16 (fp16 x fp16 -> f32), bias preloaded into the
//      accumulator from an SMEM bias tile, direct store to gmem.

namespace {

namespace wm = nvcuda::wmma;

constexpr int BSZ   = 2;
constexpr int NQ    = 32768;
constexpr int CH    = 128;
constexpr int NV    = 40960;
constexpr int NSAMP = 16;   // NL*NP
constexpr int NOFF  = 32;   // NL*NP*2
constexpr int WARPS = 8;    // warps per CTA
constexpr int QPW   = 4;    // queries per warp
constexpr int QPC   = WARPS * QPW;   // 32 queries per CTA
constexpr int SLD   = 136;  // fp16 samp row stride (halfs), 272B rows

constexpr size_t VAL_ELEMS = (size_t)BSZ * NV * CH;   // 10,485,760

typedef unsigned long long ull;

__device__ __half g_val_h[VAL_ELEMS];                 // 21 MB scratch
// Packed projection weights: [k/2][sample j] = 8 fp16:
//   {offx(k0,j), offy(k0,j), attn(k0,j), 0, offx(k1,j), offy(k1,j), attn(k1,j), 0}
__device__ uint4 g_wpack[CH / 2][NSAMP];
// fp16 copy of W_out [k][c] row-major (32 KB, L1-resident during Phase C)
__device__ __half g_wout_h[CH * CH];

// ---- f32x2 helpers ---------------------------------------------------------
__device__ __forceinline__ ull pack2(float lo, float hi)
{
    ull r;
    asm("mov.b64 %0, {%1, %2};" : "=l"(r) : "f"(lo), "f"(hi));
    return r;
}
__device__ __forceinline__ float2 unpack2(ull v)
{
    float2 f;
    asm("mov.b64 {%0, %1}, %2;" : "=f"(f.x), "=f"(f.y) : "l"(v));
    return f;
}
__device__ __forceinline__ void fma2(ull& acc, ull a, ull b)
{
    asm("fma.rn.f32x2 %0, %1, %2, %0;" : "+l"(acc) : "l"(a), "l"(b));
}
// half2 (as u32) -> packed f32x2 (as u64)
__device__ __forceinline__ ull h2f2(unsigned int h)
{
    ull r;
    asm("{\n\t"
        ".reg .f16 lo, hi;\n\t"
        ".reg .f32 flo, fhi;\n\t"
        "mov.b32 {lo, hi}, %1;\n\t"
        "cvt.f32.f16 flo, lo;\n\t"
        "cvt.f32.f16 fhi, hi;\n\t"
        "mov.b64 %0, {flo, fhi};\n\t"
        "}"
        : "=l"(r) : "r"(h));
    return r;
}

// ---- prep: value fp32->fp16 + weight packing (fused) ------------------------
__global__ void __launch_bounds__(256) convert_value(
    const float* __restrict__ v,
    const float* __restrict__ Woff, const float* __restrict__ Wattn,
    const float* __restrict__ Wout)
{
    const size_t i = ((size_t)blockIdx.x * 256 + threadIdx.x) * 4;
    const float4 f = *(const float4*)(v + i);
    const __half2 h0 = __floats2half2_rn(f.x, f.y);
    const __half2 h1 = __floats2half2_rn(f.z, f.w);
    uint2 u;
    u.x = *(const unsigned int*)&h0;
    u.y = *(const unsigned int*)&h1;
    *(uint2*)(g_val_h + i) = u;

    if (blockIdx.x == 0) {
        // projection-weight packing
        for (int idx = threadIdx.x; idx < (CH / 2) * NSAMP; idx += 256) {
            const int k2 = idx >> 4;
            const int j  = idx & 15;
            const int k0 = 2 * k2, k1 = 2 * k2 + 1;
            const __half2 a0 = __floats2half2_rn(Woff[k0 * NOFF + 2 * j],
                                                 Woff[k0 * NOFF + 2 * j + 1]);
            const __half2 a1 = __floats2half2_rn(Wattn[k0 * NSAMP + j], 0.f);
            const __half2 a2 = __floats2half2_rn(Woff[k1 * NOFF + 2 * j],
                                                 Woff[k1 * NOFF + 2 * j + 1]);
            const __half2 a3 = __floats2half2_rn(Wattn[k1 * NSAMP + j], 0.f);
            uint4 w;
            w.x = *(const unsigned int*)&a0;
            w.y = *(const unsigned int*)&a1;
            w.z = *(const unsigned int*)&a2;
            w.w = *(const unsigned int*)&a3;
            g_wpack[k2][j] = w;
        }
    } else if (blockIdx.x == 1) {
        // W_out fp16 copy (row-major, same layout)
        for (int idx = threadIdx.x; idx < CH * CH / 2; idx += 256) {
            const float2 wv = ((const float2*)Wout)[idx];
            const __half2 hw = __floats2half2_rn(wv.x, wv.y);
            *(unsigned int*)&g_wout_h[2 * idx] = *(const unsigned int*)&hw;
        }
    }
}

// Accumulate 8 fp16 channels (one uint4) with weight w into 4 packed f32x2.
__device__ __forceinline__ void acc8p(ull* ac, float w, const uint4& u)
{
    const ull wd = pack2(w, w);
    fma2(ac[0], wd, h2f2(u.x));
    fma2(ac[1], wd, h2f2(u.y));
    fma2(ac[2], wd, h2f2(u.z));
    fma2(ac[3], wd, h2f2(u.w));
}

__global__ void __launch_bounds__(WARPS * 32, 5) msda_fused(
    const float* __restrict__ query,
    const float* __restrict__ qloc,
    const float* __restrict__ boff,
    const float* __restrict__ battn,
    const float* __restrict__ bout,
    float* __restrict__ out)
{
    // Query-vector staging (Phase A), padded stride 33.
    __shared__ float4 tbuf[QPC][33];                  // 16.9 KB
    // Sampled vectors, fp16 row-major [q][k] for wmma A loads.
    __shared__ __half samp_h[QPC][SLD];               //  8.7 KB
    // Bias tile: 16 identical rows of bout (wmma accumulator init).
    __shared__ float sbias[16][CH];                   //  8   KB
    // Per-warp sample records (R9 format, fp32 weights), per lane-half.
    __shared__ float srec[WARPS][2][NSAMP][8];        //  8   KB

    const int tid  = threadIdx.x;
    const int warp = tid >> 5;
    const int lane = tid & 31;
    const int j16  = lane & 15;     // sample / channel-chunk owned by this lane
    const int qsel = lane >> 4;     // half 0 -> queries {0,1}, half 1 -> {2,3}
    const int qb   = blockIdx.x * QPC;
    const int q0   = qb + warp * QPW;
    const int b    = q0 >> 15;      // batch (uniform within CTA)

    // ---------------- Phase A: stage queries + packed-weight projections ----
    #pragma unroll
    for (int qq = 0; qq < QPW; qq++)
        tbuf[warp * QPW + qq][lane] =
            ((const float4*)(query + (size_t)(q0 + qq) * CH))[lane];
    // bias tile fill (uniform rows)
    for (int idx = tid; idx < 16 * CH; idx += WARPS * 32)
        sbias[idx >> 7][idx & 127] = bout[idx & 127];
    __syncwarp();

    ull   offp[2];                  // packed (ox, oy) accumulators
    float lg[2];
    {
        const float2 b2 = *(const float2*)&boff[2 * j16];
        const float  ba = battn[j16];
        offp[0] = pack2(b2.x, b2.y);
        offp[1] = offp[0];
        lg[0] = ba; lg[1] = ba;
    }

    const int row0 = warp * QPW + 2 * qsel;

    #pragma unroll 4
    for (int k4 = 0; k4 < CH / 4; k4++) {
        const uint4 wp0 = g_wpack[2 * k4 + 0][j16];   // k = 4k4, 4k4+1
        const uint4 wp1 = g_wpack[2 * k4 + 1][j16];   // k = 4k4+2, 4k4+3
        const ull o0 = h2f2(wp0.x);
        const ull o1 = h2f2(wp0.z);
        const ull o2 = h2f2(wp1.x);
        const ull o3 = h2f2(wp1.z);
        const float a0 = __half2float(__low2half(*(const __half2*)&wp0.y));
        const float a1 = __half2float(__low2half(*(const __half2*)&wp0.w));
        const float a2 = __half2float(__low2half(*(const __half2*)&wp1.y));
        const float a3 = __half2float(__low2half(*(const __half2*)&wp1.w));
        #pragma unroll
        for (int qq = 0; qq < 2; qq++) {
            const float4 qv = tbuf[row0 + qq][k4];
            fma2(offp[qq], pack2(qv.x, qv.x), o0);
            lg[qq] = fmaf(qv.x, a0, lg[qq]);
            fma2(offp[qq], pack2(qv.y, qv.y), o1);
            lg[qq] = fmaf(qv.y, a1, lg[qq]);
            fma2(offp[qq], pack2(qv.z, qv.z), o2);
            lg[qq] = fmaf(qv.z, a2, lg[qq]);
            fma2(offp[qq], pack2(qv.w, qv.w), o3);
            lg[qq] = fmaf(qv.w, a3, lg[qq]);
        }
    }

    // Level constants for the sample this lane owns.
    const int  l_own  = j16 >> 3;
    const int  Hl     = l_own ? 64 : 128;
    const int  Wl     = l_own ? 128 : 256;
    const int  startl = l_own ? 32768 : 0;
    // Gather base: this lane covers fp16 channels [8*j16, 8*j16+8)
    const char* vbh = (const char*)g_val_h + (size_t)b * NV * CH * 2 + j16 * 16;

    float (*recw)[NSAMP][8] = srec[warp];

    // ---------------- Phase B: 2 passes; each half gathers its own query ----
    #pragma unroll 1
    for (int t = 0; t < 2; t++) {
        __syncwarp();   // records of previous pass fully consumed

        const int qi_own = q0 + 2 * qsel + t;

        // softmax over 16 samples within each lane-half
        float l0 = lg[t];
        float m = l0;
        #pragma unroll
        for (int o = 8; o >= 1; o >>= 1)
            m = fmaxf(m, __shfl_xor_sync(0xffffffffu, m, o));
        const float e = __expf(l0 - m);
        float se = e;
        #pragma unroll
        for (int o = 8; o >= 1; o >>= 1)
            se += __shfl_xor_sync(0xffffffffu, se, o);
        const float aw = e / se;

        // Per-lane sample record (32 records across 2 queries at once).
        {
            const float2 ofa = unpack2(offp[t]);
            const float4 lv = *(const float4*)(qloc + (size_t)qi_own * 4);
            const float x = (l_own ? lv.z : lv.x) * (float)Wl + ofa.x - 0.5f;
            const float y = (l_own ? lv.w : lv.y) * (float)Hl + ofa.y - 0.5f;
            const float xf = floorf(x), yf = floorf(y);
            const int   x0 = (int)xf,   y0 = (int)yf;
            const float lx = x - xf,    ly = y - yf;

            const bool vx0 = (unsigned)x0 < (unsigned)Wl;
            const bool vx1 = (unsigned)(x0 + 1) < (unsigned)Wl;
            const bool vy0 = (unsigned)y0 < (unsigned)Hl;
            const bool vy1 = (unsigned)(y0 + 1) < (unsigned)Hl;

            const float w00 = (vx0 && vy0) ? (1.f - lx) * (1.f - ly) * aw : 0.f;
            const float w10 = (vx1 && vy0) ? lx * (1.f - ly) * aw : 0.f;
            const float w01 = (vx0 && vy1) ? (1.f - lx) * ly * aw : 0.f;
            const float w11 = (vx1 && vy1) ? lx * ly * aw : 0.f;

            const int cx0 = min(max(x0, 0), Wl - 1);
            const int cx1 = min(max(x0 + 1, 0), Wl - 1);
            const int cy0 = min(max(y0, 0), Hl - 1) * Wl + startl;
            const int cy1 = min(max(y0 + 1, 0), Hl - 1) * Wl + startl;

            const int o00 = (cy0 + cx0) << 8;   // 256 B per fp16 value row
            const int o10 = (cy0 + cx1) << 8;
            const int o01 = (cy1 + cx0) << 8;
            const int o11 = (cy1 + cx1) << 8;

            *(float4*)&recw[qsel][j16][0] = make_float4(
                __int_as_float(o00), __int_as_float(o10),
                __int_as_float(o01), __int_as_float(o11));
            *(float4*)&recw[qsel][j16][4] = make_float4(w00, w10, w01, w11);
        }
        __syncwarp();

        // Gather: each half loads full 256B corner rows with LDG.128.
        ull ac[4];
        ac[0] = ac[1] = ac[2] = ac[3] = pack2(0.f, 0.f);
        #pragma unroll
        for (int s = 0; s < NSAMP; s++) {
            const float4 ro = *(const float4*)&recw[qsel][s][0];
            const float4 rw = *(const float4*)&recw[qsel][s][4];
            const uint4 u00 = *(const uint4*)(vbh + __float_as_int(ro.x));
            const uint4 u10 = *(const uint4*)(vbh + __float_as_int(ro.y));
            const uint4 u01 = *(const uint4*)(vbh + __float_as_int(ro.z));
            const uint4 u11 = *(const uint4*)(vbh + __float_as_int(ro.w));
            acc8p(ac, rw.x, u00);
            acc8p(ac, rw.y, u10);
            acc8p(ac, rw.z, u01);
            acc8p(ac, rw.w, u11);
        }

        // fp16 stash, row-major [q][k]: lane covers channels [8*j16, 8*j16+8)
        {
            const int qidx = warp * QPW + 2 * qsel + t;
            const float2 p0 = unpack2(ac[0]);
            const float2 p1 = unpack2(ac[1]);
            const float2 p2 = unpack2(ac[2]);
            const float2 p3 = unpack2(ac[3]);
            const __half2 s0 = __floats2half2_rn(p0.x, p0.y);
            const __half2 s1 = __floats2half2_rn(p1.x, p1.y);
            const __half2 s2 = __floats2half2_rn(p2.x, p2.y);
            const __half2 s3 = __floats2half2_rn(p3.x, p3.y);
            uint4 st;
            st.x = *(const unsigned int*)&s0;
            st.y = *(const unsigned int*)&s1;
            st.z = *(const unsigned int*)&s2;
            st.w = *(const unsigned int*)&s3;
            *(uint4*)&samp_h[qidx][8 * j16] = st;
        }
    }
    __syncthreads();    // all sampled vectors visible CTA-wide

    // ---------------- Phase C: wmma output projection ------------------------
    // Tiles: 2 m-tiles (16 queries) x 8 n-tiles (16 cols).  Warp w handles
    // m-tile (w&1) and n-tiles {2*(w>>1), 2*(w>>1)+1}.  8 k-steps of 16.
    {
        const int mt = warp & 1;
        const int nt = (warp >> 1) * 2;

        wm::fragment<wm::accumulator, 16, 16, 16, float> acc0, acc1;
        wm::load_matrix_sync(acc0, &sbias[0][nt * 16], CH, wm::mem_row_major);
        wm::load_matrix_sync(acc1, &sbias[0][nt * 16 + 16], CH, wm::mem_row_major);

        #pragma unroll
        for (int ks = 0; ks < CH / 16; ks++) {
            wm::fragment<wm::matrix_a, 16, 16, 16, __half, wm::row_major> af;
            wm::load_matrix_sync(af, &samp_h[mt * 16][ks * 16], SLD);
            wm::fragment<wm::matrix_b, 16, 16, 16, __half, wm::row_major> bf0, bf1;
            wm::load_matrix_sync(bf0, g_wout_h + ks * 16 * CH + nt * 16, CH);
            wm::load_matrix_sync(bf1, g_wout_h + ks * 16 * CH + nt * 16 + 16, CH);
            wm::mma_sync(acc0, af, bf0, acc0);
            wm::mma_sync(acc1, af, bf1, acc1);
        }

        float* ob = out + (size_t)(qb + mt * 16) * CH;
        wm::store_matrix_sync(ob + nt * 16, acc0, CH, wm::mem_row_major);
        wm::store_matrix_sync(ob + nt * 16 + 16, acc1, CH, wm::mem_row_major);
    }
}

} // namespace

extern "C" void kernel_launch(void* const* d_in, const int* in_sizes, int n_in,
                              void* d_out, int out_size)
{
    const float* query = (const float*)d_in[0];
    const float* value = (const float*)d_in[1];
    const float* qloc  = (const float*)d_in[2];
    const float* Woff  = (const float*)d_in[5];
    const float* boff  = (const float*)d_in[6];
    const float* Wattn = (const float*)d_in[7];
    const float* battn = (const float*)d_in[8];
    const float* Wout  = (const float*)d_in[9];
    const float* bout  = (const float*)d_in[10];

    // Fused prep: value fp32 -> fp16 + projection/output weight packing
    constexpr int conv_blocks = (int)(VAL_ELEMS / 4 / 256);   // 10240
    convert_value<<<conv_blocks, 256>>>(value, Woff, Wattn, Wout);

    constexpr int blocks = (BSZ * NQ) / QPC;     // 2048
    msda_fused<<<blocks, WARPS * 32>>>(query, qloc, boff, battn,
                                       bout, (float*)d_out);
}

// round 12
// speedup vs baseline: 1.1962x; 1.1481x over previous
#include <cuda_runtime.h>
#include <cuda_fp16.h>
#include <mma.h>

// Multi-scale deformable attention, fully fused (round 12).
// Fixed constants: BS=2, NQ=32768, C=128, NH=1, NL=2, NP=8
//   level 0: H=128,W=256,start=0 ; level 1: H=64,W=128,start=32768 ; NV=40960
//
// R12: SMEM union (tbuf aliased with samp+srec, 42->17KB), 6 CTAs/SM,
//      Phase C one n-tile per warp (halved global B-fragment loads),
//      bias tile read from global scratch.

namespace {

namespace wm = nvcuda::wmma;

constexpr int BSZ   = 2;
constexpr int NQ    = 32768;
constexpr int CH    = 128;
constexpr int NV    = 40960;
constexpr int NSAMP = 16;   // NL*NP
constexpr int NOFF  = 32;   // NL*NP*2
constexpr int WARPS = 8;    // warps per CTA
constexpr int QPW   = 4;    // queries per warp
constexpr int QPC   = WARPS * QPW;   // 32 queries per CTA
constexpr int SLD   = 136;  // fp16 samp row stride (halfs), 272B rows

constexpr size_t VAL_ELEMS = (size_t)BSZ * NV * CH;   // 10,485,760

// SMEM union sizes
constexpr int SAMP_BYTES = QPC * SLD * 2;             // 8704
constexpr int SREC_BYTES = WARPS * 2 * NSAMP * 8 * 4; // 8192
constexpr int TBUF_BYTES = QPC * 33 * 16;             // 16896
constexpr int SMEM_BYTES = (SAMP_BYTES + SREC_BYTES) > TBUF_BYTES
                         ? (SAMP_BYTES + SREC_BYTES) : TBUF_BYTES;

typedef unsigned long long ull;

__device__ __half g_val_h[VAL_ELEMS + 256];           // 21 MB (+pad)
// Packed projection weights: [k/2][sample j] = 8 fp16:
//   {offx(k0,j), offy(k0,j), attn(k0,j), 0, offx(k1,j), offy(k1,j), attn(k1,j), 0}
__device__ uint4 g_wpack[CH / 2][NSAMP];
// fp16 copy of W_out [k][c] row-major (32 KB, L1-resident during Phase C)
__device__ __half g_wout_h[CH * CH];
// 16 identical rows of bout (f32) for wmma accumulator init
__device__ float g_bias16[16 * CH];

// ---- f32x2 helpers ---------------------------------------------------------
__device__ __forceinline__ ull pack2(float lo, float hi)
{
    ull r;
    asm("mov.b64 %0, {%1, %2};" : "=l"(r) : "f"(lo), "f"(hi));
    return r;
}
__device__ __forceinline__ float2 unpack2(ull v)
{
    float2 f;
    asm("mov.b64 {%0, %1}, %2;" : "=f"(f.x), "=f"(f.y) : "l"(v));
    return f;
}
__device__ __forceinline__ void fma2(ull& acc, ull a, ull b)
{
    asm("fma.rn.f32x2 %0, %1, %2, %0;" : "+l"(acc) : "l"(a), "l"(b));
}
// half2 (as u32) -> packed f32x2 (as u64)
__device__ __forceinline__ ull h2f2(unsigned int h)
{
    ull r;
    asm("{\n\t"
        ".reg .f16 lo, hi;\n\t"
        ".reg .f32 flo, fhi;\n\t"
        "mov.b32 {lo, hi}, %1;\n\t"
        "cvt.f32.f16 flo, lo;\n\t"
        "cvt.f32.f16 fhi, hi;\n\t"
        "mov.b64 %0, {flo, fhi};\n\t"
        "}"
        : "=l"(r) : "r"(h));
    return r;
}

// ---- prep: value fp32->fp16 + weight/bias packing (fused) -------------------
__global__ void __launch_bounds__(256) convert_value(
    const float* __restrict__ v,
    const float* __restrict__ Woff, const float* __restrict__ Wattn,
    const float* __restrict__ Wout, const float* __restrict__ bout)
{
    const size_t i = ((size_t)blockIdx.x * 256 + threadIdx.x) * 4;
    const float4 f = *(const float4*)(v + i);
    const __half2 h0 = __floats2half2_rn(f.x, f.y);
    const __half2 h1 = __floats2half2_rn(f.z, f.w);
    uint2 u;
    u.x = *(const unsigned int*)&h0;
    u.y = *(const unsigned int*)&h1;
    *(uint2*)(g_val_h + i) = u;

    if (blockIdx.x == 0) {
        // projection-weight packing
        for (int idx = threadIdx.x; idx < (CH / 2) * NSAMP; idx += 256) {
            const int k2 = idx >> 4;
            const int j  = idx & 15;
            const int k0 = 2 * k2, k1 = 2 * k2 + 1;
            const __half2 a0 = __floats2half2_rn(Woff[k0 * NOFF + 2 * j],
                                                 Woff[k0 * NOFF + 2 * j + 1]);
            const __half2 a1 = __floats2half2_rn(Wattn[k0 * NSAMP + j], 0.f);
            const __half2 a2 = __floats2half2_rn(Woff[k1 * NOFF + 2 * j],
                                                 Woff[k1 * NOFF + 2 * j + 1]);
            const __half2 a3 = __floats2half2_rn(Wattn[k1 * NSAMP + j], 0.f);
            uint4 w;
            w.x = *(const unsigned int*)&a0;
            w.y = *(const unsigned int*)&a1;
            w.z = *(const unsigned int*)&a2;
            w.w = *(const unsigned int*)&a3;
            g_wpack[k2][j] = w;
        }
    } else if (blockIdx.x == 1) {
        // W_out fp16 copy (row-major, same layout)
        for (int idx = threadIdx.x; idx < CH * CH / 2; idx += 256) {
            const float2 wv = ((const float2*)Wout)[idx];
            const __half2 hw = __floats2half2_rn(wv.x, wv.y);
            *(unsigned int*)&g_wout_h[2 * idx] = *(const unsigned int*)&hw;
        }
    } else if (blockIdx.x == 2) {
        // bias tile: 16 identical rows of bout
        for (int idx = threadIdx.x; idx < 16 * CH; idx += 256)
            g_bias16[idx] = bout[idx & (CH - 1)];
    }
}

// Accumulate 8 fp16 channels (one uint4) with weight w into 4 packed f32x2.
__device__ __forceinline__ void acc8p(ull* ac, float w, const uint4& u)
{
    const ull wd = pack2(w, w);
    fma2(ac[0], wd, h2f2(u.x));
    fma2(ac[1], wd, h2f2(u.y));
    fma2(ac[2], wd, h2f2(u.z));
    fma2(ac[3], wd, h2f2(u.w));
}

__global__ void __launch_bounds__(WARPS * 32, 6) msda_fused(
    const float* __restrict__ query,
    const float* __restrict__ qloc,
    const float* __restrict__ boff,
    const float* __restrict__ battn,
    float* __restrict__ out)
{
    // One 16.9 KB buffer, time-shared:
    //   Phase A: float4 tbuf[32][33]  (query vectors, padded stride)
    //   Phase B/C: __half samp[32][136]  +  float srec[8][2][16][8]
    __shared__ __align__(16) char smraw[SMEM_BYTES];
    float4 (*tbuf)[33]         = reinterpret_cast<float4(*)[33]>(smraw);
    __half (*samp_h)[SLD]      = reinterpret_cast<__half(*)[SLD]>(smraw);
    float (*srec)[2][NSAMP][8] =
        reinterpret_cast<float(*)[2][NSAMP][8]>(smraw + SAMP_BYTES);

    const int tid  = threadIdx.x;
    const int warp = tid >> 5;
    const int lane = tid & 31;
    const int j16  = lane & 15;     // sample / channel-chunk owned by this lane
    const int qsel = lane >> 4;     // half 0 -> queries {0,1}, half 1 -> {2,3}
    const int qb   = blockIdx.x * QPC;
    const int q0   = qb + warp * QPW;
    const int b    = q0 >> 15;      // batch (uniform within CTA)

    // ---------------- Phase A: stage queries + packed-weight projections ----
    #pragma unroll
    for (int qq = 0; qq < QPW; qq++)
        tbuf[warp * QPW + qq][lane] =
            ((const float4*)(query + (size_t)(q0 + qq) * CH))[lane];
    __syncwarp();

    ull   offp[2];                  // packed (ox, oy) accumulators
    float lg[2];
    {
        const float2 b2 = *(const float2*)&boff[2 * j16];
        const float  ba = battn[j16];
        offp[0] = pack2(b2.x, b2.y);
        offp[1] = offp[0];
        lg[0] = ba; lg[1] = ba;
    }

    const int row0 = warp * QPW + 2 * qsel;

    #pragma unroll 4
    for (int k4 = 0; k4 < CH / 4; k4++) {
        const uint4 wp0 = g_wpack[2 * k4 + 0][j16];   // k = 4k4, 4k4+1
        const uint4 wp1 = g_wpack[2 * k4 + 1][j16];   // k = 4k4+2, 4k4+3
        const ull o0 = h2f2(wp0.x);
        const ull o1 = h2f2(wp0.z);
        const ull o2 = h2f2(wp1.x);
        const ull o3 = h2f2(wp1.z);
        const float a0 = __half2float(__low2half(*(const __half2*)&wp0.y));
        const float a1 = __half2float(__low2half(*(const __half2*)&wp0.w));
        const float a2 = __half2float(__low2half(*(const __half2*)&wp1.y));
        const float a3 = __half2float(__low2half(*(const __half2*)&wp1.w));
        #pragma unroll
        for (int qq = 0; qq < 2; qq++) {
            const float4 qv = tbuf[row0 + qq][k4];
            fma2(offp[qq], pack2(qv.x, qv.x), o0);
            lg[qq] = fmaf(qv.x, a0, lg[qq]);
            fma2(offp[qq], pack2(qv.y, qv.y), o1);
            lg[qq] = fmaf(qv.y, a1, lg[qq]);
            fma2(offp[qq], pack2(qv.z, qv.z), o2);
            lg[qq] = fmaf(qv.z, a2, lg[qq]);
            fma2(offp[qq], pack2(qv.w, qv.w), o3);
            lg[qq] = fmaf(qv.w, a3, lg[qq]);
        }
    }
    __syncthreads();    // ALL warps done reading tbuf before samp/srec writes

    // Level constants for the sample this lane owns.
    const int  l_own  = j16 >> 3;
    const int  Hl     = l_own ? 64 : 128;
    const int  Wl     = l_own ? 128 : 256;
    const int  startl = l_own ? 32768 : 0;
    // Gather base: this lane covers fp16 channels [8*j16, 8*j16+8)
    const char* vbh = (const char*)g_val_h + (size_t)b * NV * CH * 2 + j16 * 16;

    float (*recw)[NSAMP][8] = srec[warp];

    // ---------------- Phase B: 2 passes; each half gathers its own query ----
    #pragma unroll 1
    for (int t = 0; t < 2; t++) {
        __syncwarp();   // records of previous pass fully consumed

        const int qi_own = q0 + 2 * qsel + t;

        // softmax over 16 samples within each lane-half
        float l0 = lg[t];
        float m = l0;
        #pragma unroll
        for (int o = 8; o >= 1; o >>= 1)
            m = fmaxf(m, __shfl_xor_sync(0xffffffffu, m, o));
        const float e = __expf(l0 - m);
        float se = e;
        #pragma unroll
        for (int o = 8; o >= 1; o >>= 1)
            se += __shfl_xor_sync(0xffffffffu, se, o);
        const float aw = e / se;

        // Per-lane sample record (32 records across 2 queries at once).
        {
            const float2 ofa = unpack2(offp[t]);
            const float4 lv = *(const float4*)(qloc + (size_t)qi_own * 4);
            const float x = (l_own ? lv.z : lv.x) * (float)Wl + ofa.x - 0.5f;
            const float y = (l_own ? lv.w : lv.y) * (float)Hl + ofa.y - 0.5f;
            const float xf = floorf(x), yf = floorf(y);
            const int   x0 = (int)xf,   y0 = (int)yf;
            const float lx = x - xf,    ly = y - yf;

            const bool vx0 = (unsigned)x0 < (unsigned)Wl;
            const bool vx1 = (unsigned)(x0 + 1) < (unsigned)Wl;
            const bool vy0 = (unsigned)y0 < (unsigned)Hl;
            const bool vy1 = (unsigned)(y0 + 1) < (unsigned)Hl;

            const float w00 = (vx0 && vy0) ? (1.f - lx) * (1.f - ly) * aw : 0.f;
            const float w10 = (vx1 && vy0) ? lx * (1.f - ly) * aw : 0.f;
            const float w01 = (vx0 && vy1) ? (1.f - lx) * ly * aw : 0.f;
            const float w11 = (vx1 && vy1) ? lx * ly * aw : 0.f;

            const int cx0 = min(max(x0, 0), Wl - 1);
            const int cx1 = min(max(x0 + 1, 0), Wl - 1);
            const int cy0 = min(max(y0, 0), Hl - 1) * Wl + startl;
            const int cy1 = min(max(y0 + 1, 0), Hl - 1) * Wl + startl;

            const int o00 = (cy0 + cx0) << 8;   // 256 B per fp16 value row
            const int o10 = (cy0 + cx1) << 8;
            const int o01 = (cy1 + cx0) << 8;
            const int o11 = (cy1 + cx1) << 8;

            *(float4*)&recw[qsel][j16][0] = make_float4(
                __int_as_float(o00), __int_as_float(o10),
                __int_as_float(o01), __int_as_float(o11));
            *(float4*)&recw[qsel][j16][4] = make_float4(w00, w10, w01, w11);
        }
        __syncwarp();

        // Gather: each half loads full 256B corner rows with LDG.128.
        ull ac[4];
        ac[0] = ac[1] = ac[2] = ac[3] = pack2(0.f, 0.f);
        #pragma unroll
        for (int s = 0; s < NSAMP; s++) {
            const float4 ro = *(const float4*)&recw[qsel][s][0];
            const float4 rw = *(const float4*)&recw[qsel][s][4];
            const uint4 u00 = *(const uint4*)(vbh + __float_as_int(ro.x));
            const uint4 u10 = *(const uint4*)(vbh + __float_as_int(ro.y));
            const uint4 u01 = *(const uint4*)(vbh + __float_as_int(ro.z));
            const uint4 u11 = *(const uint4*)(vbh + __float_as_int(ro.w));
            acc8p(ac, rw.x, u00);
            acc8p(ac, rw.y, u10);
            acc8p(ac, rw.z, u01);
            acc8p(ac, rw.w, u11);
        }

        // fp16 stash, row-major [q][k]: lane covers channels [8*j16, 8*j16+8)
        {
            const int qidx = warp * QPW + 2 * qsel + t;
            const float2 p0 = unpack2(ac[0]);
            const float2 p1 = unpack2(ac[1]);
            const float2 p2 = unpack2(ac[2]);
            const float2 p3 = unpack2(ac[3]);
            const __half2 s0 = __floats2half2_rn(p0.x, p0.y);
            const __half2 s1 = __floats2half2_rn(p1.x, p1.y);
            const __half2 s2 = __floats2half2_rn(p2.x, p2.y);
            const __half2 s3 = __floats2half2_rn(p3.x, p3.y);
            uint4 st;
            st.x = *(const unsigned int*)&s0;
            st.y = *(const unsigned int*)&s1;
            st.z = *(const unsigned int*)&s2;
            st.w = *(const unsigned int*)&s3;
            *(uint4*)&samp_h[qidx][8 * j16] = st;
        }
    }
    __syncthreads();    // all sampled vectors visible CTA-wide

    // ---------------- Phase C: wmma output projection ------------------------
    // Warp w owns n-tile w (cols 16w..16w+15) for BOTH m-tiles: B fragments
    // loaded once per (ks, nt) CTA-wide.  8 k-steps of 16.
    {
        const int nt = warp;

        wm::fragment<wm::accumulator, 16, 16, 16, float> acc0, acc1;
        wm::load_matrix_sync(acc0, g_bias16 + nt * 16, CH, wm::mem_row_major);
        acc1 = acc0;

        #pragma unroll
        for (int ks = 0; ks < CH / 16; ks++) {
            wm::fragment<wm::matrix_b, 16, 16, 16, __half, wm::row_major> bf;
            wm::load_matrix_sync(bf, g_wout_h + ks * 16 * CH + nt * 16, CH);
            wm::fragment<wm::matrix_a, 16, 16, 16, __half, wm::row_major> a0, a1;
            wm::load_matrix_sync(a0, &samp_h[0][ks * 16], SLD);
            wm::load_matrix_sync(a1, &samp_h[16][ks * 16], SLD);
            wm::mma_sync(acc0, a0, bf, acc0);
            wm::mma_sync(acc1, a1, bf, acc1);
        }

        float* ob = out + (size_t)qb * CH + nt * 16;
        wm::store_matrix_sync(ob, acc0, CH, wm::mem_row_major);
        wm::store_matrix_sync(ob + (size_t)16 * CH, acc1, CH, wm::mem_row_major);
    }
}

} // namespace

extern "C" void kernel_launch(void* const* d_in, const int* in_sizes, int n_in,
                              void* d_out, int out_size)
{
    const float* query = (const float*)d_in[0];
    const float* value = (const float*)d_in[1];
    const float* qloc  = (const float*)d_in[2];
    const float* Woff  = (const float*)d_in[5];
    const float* boff  = (const float*)d_in[6];
    const float* Wattn = (const float*)d_in[7];
    const float* battn = (const float*)d_in[8];
    const float* Wout  = (const float*)d_in[9];
    const float* bout  = (const float*)d_in[10];

    // Fused prep: value fp32 -> fp16 + projection/output weight + bias packing
    constexpr int conv_blocks = (int)(VAL_ELEMS / 4 / 256);   // 10240
    convert_value<<<conv_blocks, 256>>>(value, Woff, Wattn, Wout, bout);

    constexpr int blocks = (BSZ * NQ) / QPC;     // 2048
    msda_fused<<<blocks, WARPS * 32>>>(query, qloc, boff, battn, (float*)d_out);
}